// round 10
// baseline (speedup 1.0000x reference)
#include <cuda_runtime.h>
#include <cuda_bf16.h>
#include <mma.h>
#include <cstdint>

using namespace nvcuda;

#define MAX_NODES_PAD 100096   // 782 * 128
#define MAX_EDGES 700000
#define D 128
#define D4 (D / 4)
#define NCH 8                  // gather/gemm2 pipeline chunks

// Scratch (device globals; rebuilt every replay)
__device__ int g_deg[MAX_NODES_PAD];
__device__ int g_rowstart[MAX_NODES_PAD];
__device__ int g_cursor[MAX_NODES_PAD];
__device__ int g_bsum[256];
__device__ int g_adj[2 * MAX_EDGES];
__device__ float g_Z[(size_t)MAX_NODES_PAD * D];            // X @ Wh
__device__ __nv_bfloat16 g_Hhi[(size_t)MAX_NODES_PAD * D];  // split relu(Zagg + bh)
__device__ __nv_bfloat16 g_Hlo[(size_t)MAX_NODES_PAD * D];

// ===========================================================================
// CSR build
// ===========================================================================
__global__ void zero_deg_kernel(int n) {
    int i = blockIdx.x * blockDim.x + threadIdx.x;
    if (i < n) g_deg[i] = 0;
}

__global__ void hist_kernel(const int* __restrict__ ra, const int* __restrict__ rb, int n_edges) {
    int e = blockIdx.x * blockDim.x + threadIdx.x;
    if (e >= n_edges) return;
    atomicAdd(&g_deg[ra[e]], 1);
    atomicAdd(&g_deg[rb[e]], 1);
}

__global__ void scan_block_kernel(int n) {
    __shared__ int wsum[32];
    int i = blockIdx.x * 1024 + threadIdx.x;
    int lane = threadIdx.x & 31, w = threadIdx.x >> 5;
    int v = (i < n) ? g_deg[i] : 0;
    int s = v;
    #pragma unroll
    for (int o = 1; o < 32; o <<= 1) {
        int t = __shfl_up_sync(0xFFFFFFFFu, s, o);
        if (lane >= o) s += t;
    }
    if (lane == 31) wsum[w] = s;
    __syncthreads();
    if (threadIdx.x < 32) {
        int t = wsum[threadIdx.x];
        int sc = t;
        #pragma unroll
        for (int o = 1; o < 32; o <<= 1) {
            int u = __shfl_up_sync(0xFFFFFFFFu, sc, o);
            if (lane >= o) sc += u;
        }
        wsum[threadIdx.x] = sc - t;
        if (threadIdx.x == 31) g_bsum[blockIdx.x] = sc;
    }
    __syncthreads();
    if (i < n) g_rowstart[i] = (s - v) + wsum[w];
}

__global__ void scan_top_kernel(int nb) {
    __shared__ int sm[256];
    int t = threadIdx.x;
    int v = (t < nb) ? g_bsum[t] : 0;
    sm[t] = v;
    __syncthreads();
    #pragma unroll
    for (int o = 1; o < 256; o <<= 1) {
        int u = (t >= o) ? sm[t - o] : 0;
        __syncthreads();
        sm[t] += u;
        __syncthreads();
    }
    if (t < nb) g_bsum[t] = sm[t] - v;
}

__global__ void scan_add_kernel(int n) {
    int i = blockIdx.x * 1024 + threadIdx.x;
    if (i < n) {
        int rs = g_rowstart[i] + g_bsum[blockIdx.x];
        g_rowstart[i] = rs;
        g_cursor[i] = rs;
    }
}

__global__ void fill_adj_kernel(const int* __restrict__ ra, const int* __restrict__ rb, int n_edges) {
    int e = blockIdx.x * blockDim.x + threadIdx.x;
    if (e >= n_edges) return;
    int a = ra[e], b = rb[e];
    int p = atomicAdd(&g_cursor[a], 1);
    g_adj[p] = b;
    int q = atomicAdd(&g_cursor[b], 1);
    g_adj[q] = a;
}

// ===========================================================================
// Shared GEMM plumbing
// ===========================================================================
#define LDA 136

__device__ __forceinline__ void split2(float x, __nv_bfloat16& hi, __nv_bfloat16& lo) {
    hi = __float2bfloat16_rn(x);
    lo = __float2bfloat16_rn(x - __bfloat162float(hi));
}

typedef wmma::fragment<wmma::matrix_a, 16, 16, 16, __nv_bfloat16, wmma::row_major> FragA;
typedef wmma::fragment<wmma::matrix_b, 16, 16, 16, __nv_bfloat16, wmma::row_major> FragB;
typedef wmma::fragment<wmma::accumulator, 16, 16, 16, float> FragC;

// ===========================================================================
// Kernel Z: Z = X @ Wh   (bf16x3; overlaps CSR build on a forked stream)
// ===========================================================================
#define SMZ_AHI 0
#define SMZ_ALO (128 * LDA * 2)
#define SMZ_WHI (2 * 128 * LDA * 2)
#define SMZ_WLO (3 * 128 * LDA * 2)
#define SMZ_TOTAL (4 * 128 * LDA * 2)   // 139264

__global__ __launch_bounds__(512, 1)
void zgemm_kernel(const float* __restrict__ X, const float* __restrict__ Wh, int n_nodes) {
    extern __shared__ char smem[];
    __nv_bfloat16* Ahi = (__nv_bfloat16*)(smem + SMZ_AHI);
    __nv_bfloat16* Alo = (__nv_bfloat16*)(smem + SMZ_ALO);
    __nv_bfloat16* Whi = (__nv_bfloat16*)(smem + SMZ_WHI);
    __nv_bfloat16* Wlo = (__nv_bfloat16*)(smem + SMZ_WLO);

    const int tid = threadIdx.x;
    const int wid = tid >> 5;
    const int row0 = blockIdx.x * 128;

    const float4* X4 = (const float4*)X;
    #pragma unroll
    for (int it = 0; it < 8; ++it) {
        int i = tid + it * 512;
        int r = i >> 5, c = (i & 31) * 4;
        float4 v = make_float4(0.f, 0.f, 0.f, 0.f);
        if (row0 + r < n_nodes) v = X4[(size_t)(row0 + r) * D4 + (c >> 2)];
        __nv_bfloat16 h0, l0, h1, l1, h2, l2, h3, l3;
        split2(v.x, h0, l0); split2(v.y, h1, l1);
        split2(v.z, h2, l2); split2(v.w, h3, l3);
        int o = r * LDA + c;
        Ahi[o] = h0; Ahi[o+1] = h1; Ahi[o+2] = h2; Ahi[o+3] = h3;
        Alo[o] = l0; Alo[o+1] = l1; Alo[o+2] = l2; Alo[o+3] = l3;
    }
    {
        const float4* W4 = (const float4*)Wh;
        #pragma unroll
        for (int it = 0; it < 8; ++it) {
            int i = tid + it * 512;
            int k = i >> 5, c = (i & 31) * 4;
            float4 v = W4[i];
            __nv_bfloat16 h0, l0, h1, l1, h2, l2, h3, l3;
            split2(v.x, h0, l0); split2(v.y, h1, l1);
            split2(v.z, h2, l2); split2(v.w, h3, l3);
            int o = k * LDA + c;
            Whi[o] = h0; Whi[o+1] = h1; Whi[o+2] = h2; Whi[o+3] = h3;
            Wlo[o] = l0; Wlo[o+1] = l1; Wlo[o+2] = l2; Wlo[o+3] = l3;
        }
    }
    __syncthreads();

    const int wr = wid >> 1;
    const int wc = wid & 1;

    FragC acc[4];
    #pragma unroll
    for (int n = 0; n < 4; ++n) wmma::fill_fragment(acc[n], 0.f);
    for (int k = 0; k < 8; ++k) {
        FragA a_hi, a_lo;
        wmma::load_matrix_sync(a_hi, Ahi + wr * 16 * LDA + k * 16, LDA);
        wmma::load_matrix_sync(a_lo, Alo + wr * 16 * LDA + k * 16, LDA);
        #pragma unroll
        for (int n = 0; n < 4; ++n) {
            int nc = wc * 64 + n * 16;
            FragB b_hi, b_lo;
            wmma::load_matrix_sync(b_hi, Whi + k * 16 * LDA + nc, LDA);
            wmma::mma_sync(acc[n], a_hi, b_hi, acc[n]);
            wmma::mma_sync(acc[n], a_lo, b_hi, acc[n]);
            wmma::load_matrix_sync(b_lo, Wlo + k * 16 * LDA + nc, LDA);
            wmma::mma_sync(acc[n], a_hi, b_lo, acc[n]);
        }
    }
    float* Zt = g_Z + (size_t)(row0 + wr * 16) * D + wc * 64;
    #pragma unroll
    for (int n = 0; n < 4; ++n)
        wmma::store_matrix_sync(Zt + n * 16, acc[n], D, wmma::mem_row_major);
}

// ===========================================================================
// Gather in Z-space + bias + relu + bf16 split.  Warp-per-node, chunked.
// ===========================================================================
__global__ __launch_bounds__(256)
void gather_kernel(const float* __restrict__ bh, int node_base, int node_end) {
    int node = node_base + ((blockIdx.x * blockDim.x + threadIdx.x) >> 5);
    int lane = threadIdx.x & 31;
    if (node >= node_end) return;

    const float4* Z4 = (const float4*)g_Z;
    float4 acc = Z4[(size_t)node * D4 + lane];
    int s = g_rowstart[node];
    int e = s + g_deg[node];
    int j = s;
    for (; j + 4 <= e; j += 4) {
        int n0 = g_adj[j + 0], n1 = g_adj[j + 1];
        int n2 = g_adj[j + 2], n3 = g_adj[j + 3];
        float4 v0 = Z4[(size_t)n0 * D4 + lane];
        float4 v1 = Z4[(size_t)n1 * D4 + lane];
        float4 v2 = Z4[(size_t)n2 * D4 + lane];
        float4 v3 = Z4[(size_t)n3 * D4 + lane];
        acc.x += (v0.x + v1.x) + (v2.x + v3.x);
        acc.y += (v0.y + v1.y) + (v2.y + v3.y);
        acc.z += (v0.z + v1.z) + (v2.z + v3.z);
        acc.w += (v0.w + v1.w) + (v2.w + v3.w);
    }
    for (; j < e; ++j) {
        int nb = g_adj[j];
        float4 v = Z4[(size_t)nb * D4 + lane];
        acc.x += v.x; acc.y += v.y; acc.z += v.z; acc.w += v.w;
    }

    const float4 b4 = ((const float4*)bh)[lane];
    float x0 = fmaxf(acc.x + b4.x, 0.f);
    float x1 = fmaxf(acc.y + b4.y, 0.f);
    float x2 = fmaxf(acc.z + b4.z, 0.f);
    float x3 = fmaxf(acc.w + b4.w, 0.f);

    __nv_bfloat16 h0, l0, h1, l1, h2, l2, h3, l3;
    split2(x0, h0, l0); split2(x1, h1, l1);
    split2(x2, h2, l2); split2(x3, h3, l3);

    size_t o = (size_t)node * D + lane * 4;
    __nv_bfloat162* Hh2 = (__nv_bfloat162*)(g_Hhi + o);
    __nv_bfloat162* Hl2 = (__nv_bfloat162*)(g_Hlo + o);
    Hh2[0] = __nv_bfloat162(h0, h1);
    Hh2[1] = __nv_bfloat162(h2, h3);
    Hl2[0] = __nv_bfloat162(l0, l1);
    Hl2[1] = __nv_bfloat162(l2, l3);
}

// ===========================================================================
// GEMM2: out = H @ Wo + bo.  Chunked (tile_base offsets blockIdx).
// ===========================================================================
#define SM2_WHI 0
#define SM2_WLO (128 * LDA * 2)
#define SM2_BIAS (2 * 128 * LDA * 2)
#define SM2_TOTAL (SM2_BIAS + 16 * 128 * 4)    // 77824

__global__ __launch_bounds__(512, 1)
void gemm2_kernel(const float* __restrict__ Wo, const float* __restrict__ bo,
                  float* __restrict__ out, int n_nodes, int tile_base) {
    extern __shared__ char smem[];
    __nv_bfloat16* Whi = (__nv_bfloat16*)(smem + SM2_WHI);
    __nv_bfloat16* Wlo = (__nv_bfloat16*)(smem + SM2_WLO);
    float*         bias_s = (float*)(smem + SM2_BIAS);

    const int tid = threadIdx.x;
    const int wid = tid >> 5;
    const int row0 = (tile_base + blockIdx.x) * 128;

    {
        const float4* W4 = (const float4*)Wo;
        #pragma unroll
        for (int it = 0; it < 8; ++it) {
            int i = tid + it * 512;
            int k = i >> 5, c = (i & 31) * 4;
            float4 v = W4[i];
            __nv_bfloat16 h0, l0, h1, l1, h2, l2, h3, l3;
            split2(v.x, h0, l0); split2(v.y, h1, l1);
            split2(v.z, h2, l2); split2(v.w, h3, l3);
            int o = k * LDA + c;
            Whi[o] = h0; Whi[o+1] = h1; Whi[o+2] = h2; Whi[o+3] = h3;
            Wlo[o] = l0; Wlo[o+1] = l1; Wlo[o+2] = l2; Wlo[o+3] = l3;
        }
    }
    #pragma unroll
    for (int it = 0; it < 4; ++it) {
        int i = tid + it * 512;
        bias_s[i] = bo[i & 127];
    }
    __syncthreads();

    const int wr = wid >> 1;
    const int wc = wid & 1;

    FragC acc[4];
    #pragma unroll
    for (int n = 0; n < 4; ++n)
        wmma::load_matrix_sync(acc[n], bias_s + wc * 64 + n * 16, 128, wmma::mem_row_major);

    const __nv_bfloat16* Ah = g_Hhi + (size_t)(row0 + wr * 16) * D;
    const __nv_bfloat16* Al = g_Hlo + (size_t)(row0 + wr * 16) * D;
    for (int k = 0; k < 8; ++k) {
        FragA a_hi, a_lo;
        wmma::load_matrix_sync(a_hi, Ah + k * 16, D);
        wmma::load_matrix_sync(a_lo, Al + k * 16, D);
        #pragma unroll
        for (int n = 0; n < 4; ++n) {
            int nc = wc * 64 + n * 16;
            FragB b_hi, b_lo;
            wmma::load_matrix_sync(b_hi, Whi + k * 16 * LDA + nc, LDA);
            wmma::mma_sync(acc[n], a_hi, b_hi, acc[n]);
            wmma::mma_sync(acc[n], a_lo, b_hi, acc[n]);
            wmma::load_matrix_sync(b_lo, Wlo + k * 16 * LDA + nc, LDA);
            wmma::mma_sync(acc[n], a_hi, b_lo, acc[n]);
        }
    }

    if (row0 + 128 <= n_nodes) {
        float* Ot = out + (size_t)(row0 + wr * 16) * D + wc * 64;
        #pragma unroll
        for (int n = 0; n < 4; ++n)
            wmma::store_matrix_sync(Ot + n * 16, acc[n], D, wmma::mem_row_major);
    } else {
        __syncthreads();
        float* stage = (float*)(smem + SM2_WHI);
        #pragma unroll
        for (int n = 0; n < 4; ++n)
            wmma::store_matrix_sync(stage + (wr * 16) * 128 + wc * 64 + n * 16,
                                    acc[n], 128, wmma::mem_row_major);
        __syncthreads();
        #pragma unroll
        for (int it = 0; it < 8; ++it) {
            int i = tid + it * 512;
            int r = i >> 5, c = (i & 31) * 4;
            if (row0 + r < n_nodes)
                *(float4*)&out[(size_t)(row0 + r) * D + c] = *(float4*)&stage[r * 128 + c];
        }
    }
}

// ===========================================================================
extern "C" void kernel_launch(void* const* d_in, const int* in_sizes, int n_in,
                              void* d_out, int out_size) {
    const float* X  = (const float*)d_in[0];
    const int*   ra = (const int*)  d_in[1];
    const int*   rb = (const int*)  d_in[2];
    const float* Wh = (const float*)d_in[3];
    const float* bh = (const float*)d_in[4];
    const float* Wo = (const float*)d_in[5];
    const float* bo = (const float*)d_in[6];
    float* out = (float*)d_out;

    const int n_nodes = in_sizes[0] / D;
    const int n_edges = in_sizes[1];
    const int nb = (n_nodes + 1023) / 1024;
    const int gb = (n_nodes + 127) / 128;                 // 782 tiles
    const int tiles_per = (gb + NCH - 1) / NCH;           // 98

    cudaFuncSetAttribute(zgemm_kernel, cudaFuncAttributeMaxDynamicSharedMemorySize, SMZ_TOTAL);
    cudaFuncSetAttribute(gemm2_kernel, cudaFuncAttributeMaxDynamicSharedMemorySize, SM2_TOTAL);

    // Resources for the forked-stream DAG (leaked; created on the 2 real calls only)
    cudaStream_t s1 = nullptr;
    cudaEvent_t ev0 = nullptr, evZ = nullptr, evEnd = nullptr;
    cudaEvent_t evG[NCH] = {};
    bool forked =
        (cudaStreamCreateWithFlags(&s1, cudaStreamNonBlocking) == cudaSuccess) &&
        (cudaEventCreateWithFlags(&ev0, cudaEventDisableTiming) == cudaSuccess) &&
        (cudaEventCreateWithFlags(&evZ, cudaEventDisableTiming) == cudaSuccess) &&
        (cudaEventCreateWithFlags(&evEnd, cudaEventDisableTiming) == cudaSuccess);
    if (forked)
        for (int c = 0; c < NCH; ++c)
            if (cudaEventCreateWithFlags(&evG[c], cudaEventDisableTiming) != cudaSuccess) {
                forked = false;
                break;
            }

    if (forked) {
        // stream 0: CSR build            stream s1: Z = X @ Wh
        cudaEventRecord(ev0, 0);
        cudaStreamWaitEvent(s1, ev0, 0);
        zgemm_kernel<<<gb, 512, SMZ_TOTAL, s1>>>(X, Wh, n_nodes);
        cudaEventRecord(evZ, s1);

        zero_deg_kernel<<<(n_nodes + 255) / 256, 256>>>(n_nodes);
        hist_kernel<<<(n_edges + 255) / 256, 256>>>(ra, rb, n_edges);
        scan_block_kernel<<<nb, 1024>>>(n_nodes);
        scan_top_kernel<<<1, 256>>>(nb);
        scan_add_kernel<<<nb, 1024>>>(n_nodes);
        fill_adj_kernel<<<(n_edges + 255) / 256, 256>>>(ra, rb, n_edges);
        cudaStreamWaitEvent((cudaStream_t)0, evZ, 0);   // gather needs full Z

        // pipeline: gather(c) on stream 0, gemm2(c) on s1 (overlaps gather(c+1))
        for (int c = 0; c < NCH; ++c) {
            int t0 = c * tiles_per;
            if (t0 >= gb) break;
            int tiles = min(tiles_per, gb - t0);
            int nbase = t0 * 128;
            int nend = min(nbase + tiles * 128, n_nodes);
            int gwarps = nend - nbase;
            if (gwarps > 0) {
                int gblocks = (int)(((size_t)gwarps * 32 + 255) / 256);
                gather_kernel<<<gblocks, 256>>>(bh, nbase, nend);
            }
            cudaEventRecord(evG[c], 0);
            cudaStreamWaitEvent(s1, evG[c], 0);
            gemm2_kernel<<<tiles, 512, SM2_TOTAL, s1>>>(Wo, bo, out, n_nodes, t0);
        }
        cudaEventRecord(evEnd, s1);
        cudaStreamWaitEvent((cudaStream_t)0, evEnd, 0); // join back to origin
    } else {
        // serial fallback
        zgemm_kernel<<<gb, 512, SMZ_TOTAL>>>(X, Wh, n_nodes);
        zero_deg_kernel<<<(n_nodes + 255) / 256, 256>>>(n_nodes);
        hist_kernel<<<(n_edges + 255) / 256, 256>>>(ra, rb, n_edges);
        scan_block_kernel<<<nb, 1024>>>(n_nodes);
        scan_top_kernel<<<1, 256>>>(nb);
        scan_add_kernel<<<nb, 1024>>>(n_nodes);
        fill_adj_kernel<<<(n_edges + 255) / 256, 256>>>(ra, rb, n_edges);
        int gblocks = (int)(((size_t)n_nodes * 32 + 255) / 256);
        gather_kernel<<<gblocks, 256>>>(bh, 0, n_nodes);
        gemm2_kernel<<<gb, 512, SM2_TOTAL>>>(Wo, bo, out, n_nodes, 0);
    }
}

// round 14
// speedup vs baseline: 1.2474x; 1.2474x over previous
#include <cuda_runtime.h>
#include <cuda_bf16.h>
#include <mma.h>
#include <cstdint>

using namespace nvcuda;

#define MAX_NODES_PAD 100096   // 782 * 128
#define MAX_EDGES 700000
#define D 128
#define D4 (D / 4)

// Scratch (device globals; rebuilt every replay)
__device__ int g_deg[MAX_NODES_PAD];
__device__ int g_rowstart[MAX_NODES_PAD];
__device__ int g_cursor[MAX_NODES_PAD];
__device__ int g_bsum[256];
__device__ int g_adj[2 * MAX_EDGES];
__device__ __nv_bfloat16 g_Ahi[(size_t)MAX_NODES_PAD * D];  // split(X + sum nbr X)
__device__ __nv_bfloat16 g_Alo[(size_t)MAX_NODES_PAD * D];
__device__ __nv_bfloat16 g_Whhi[D * D], g_Whlo[D * D];      // split Wh
__device__ __nv_bfloat16 g_Wohi[D * D], g_Wolo[D * D];      // split Wo

__device__ __forceinline__ void split2(float x, __nv_bfloat16& hi, __nv_bfloat16& lo) {
    hi = __float2bfloat16_rn(x);
    lo = __float2bfloat16_rn(x - __bfloat162float(hi));
}

// ===========================================================================
// CSR build
// ===========================================================================
__global__ void zero_deg_kernel(int n) {
    int i = blockIdx.x * blockDim.x + threadIdx.x;
    if (i < n) g_deg[i] = 0;
}

__global__ void hist_kernel(const int* __restrict__ ra, const int* __restrict__ rb, int n_edges) {
    int e = blockIdx.x * blockDim.x + threadIdx.x;
    if (e >= n_edges) return;
    atomicAdd(&g_deg[ra[e]], 1);
    atomicAdd(&g_deg[rb[e]], 1);
}

__global__ void scan_block_kernel(int n) {
    __shared__ int wsum[32];
    int i = blockIdx.x * 1024 + threadIdx.x;
    int lane = threadIdx.x & 31, w = threadIdx.x >> 5;
    int v = (i < n) ? g_deg[i] : 0;
    int s = v;
    #pragma unroll
    for (int o = 1; o < 32; o <<= 1) {
        int t = __shfl_up_sync(0xFFFFFFFFu, s, o);
        if (lane >= o) s += t;
    }
    if (lane == 31) wsum[w] = s;
    __syncthreads();
    if (threadIdx.x < 32) {
        int t = wsum[threadIdx.x];
        int sc = t;
        #pragma unroll
        for (int o = 1; o < 32; o <<= 1) {
            int u = __shfl_up_sync(0xFFFFFFFFu, sc, o);
            if (lane >= o) sc += u;
        }
        wsum[threadIdx.x] = sc - t;
        if (threadIdx.x == 31) g_bsum[blockIdx.x] = sc;
    }
    __syncthreads();
    if (i < n) g_rowstart[i] = (s - v) + wsum[w];
}

__global__ void scan_top_kernel(int nb) {
    __shared__ int sm[256];
    int t = threadIdx.x;
    int v = (t < nb) ? g_bsum[t] : 0;
    sm[t] = v;
    __syncthreads();
    #pragma unroll
    for (int o = 1; o < 256; o <<= 1) {
        int u = (t >= o) ? sm[t - o] : 0;
        __syncthreads();
        sm[t] += u;
        __syncthreads();
    }
    if (t < nb) g_bsum[t] = sm[t] - v;
}

__global__ void scan_add_kernel(int n) {
    int i = blockIdx.x * 1024 + threadIdx.x;
    if (i < n) {
        int rs = g_rowstart[i] + g_bsum[blockIdx.x];
        g_rowstart[i] = rs;
        g_cursor[i] = rs;
    }
}

__global__ void fill_adj_kernel(const int* __restrict__ ra, const int* __restrict__ rb, int n_edges) {
    int e = blockIdx.x * blockDim.x + threadIdx.x;
    if (e >= n_edges) return;
    int a = ra[e], b = rb[e];
    int p = atomicAdd(&g_cursor[a], 1);
    g_adj[p] = b;
    int q = atomicAdd(&g_cursor[b], 1);
    g_adj[q] = a;
}

// ===========================================================================
// Weight pre-split: Wh, Wo (f32 [k][n]) -> bf16 hi/lo in gmem. 16384 elements.
// ===========================================================================
__global__ void wsplit_kernel(const float* __restrict__ Wh, const float* __restrict__ Wo) {
    int i = blockIdx.x * blockDim.x + threadIdx.x;   // 0..16383
    __nv_bfloat16 hi, lo;
    split2(Wh[i], hi, lo);
    g_Whhi[i] = hi; g_Whlo[i] = lo;
    split2(Wo[i], hi, lo);
    g_Wohi[i] = hi; g_Wolo[i] = lo;
}

// ===========================================================================
// Pull gather (warp-per-node) + bf16 split of aggregate.
// ===========================================================================
__global__ __launch_bounds__(256)
void gather_kernel(const float4* __restrict__ X4, int n_nodes) {
    int node = (blockIdx.x * blockDim.x + threadIdx.x) >> 5;
    int lane = threadIdx.x & 31;
    if (node >= n_nodes) return;

    float4 acc = X4[(size_t)node * D4 + lane];
    int s = g_rowstart[node];
    int e = s + g_deg[node];
    int j = s;
    for (; j + 4 <= e; j += 4) {
        int n0 = g_adj[j + 0], n1 = g_adj[j + 1];
        int n2 = g_adj[j + 2], n3 = g_adj[j + 3];
        float4 v0 = X4[(size_t)n0 * D4 + lane];
        float4 v1 = X4[(size_t)n1 * D4 + lane];
        float4 v2 = X4[(size_t)n2 * D4 + lane];
        float4 v3 = X4[(size_t)n3 * D4 + lane];
        acc.x += (v0.x + v1.x) + (v2.x + v3.x);
        acc.y += (v0.y + v1.y) + (v2.y + v3.y);
        acc.z += (v0.z + v1.z) + (v2.z + v3.z);
        acc.w += (v0.w + v1.w) + (v2.w + v3.w);
    }
    for (; j < e; ++j) {
        int nb = g_adj[j];
        float4 v = X4[(size_t)nb * D4 + lane];
        acc.x += v.x; acc.y += v.y; acc.z += v.z; acc.w += v.w;
    }

    __nv_bfloat16 h0, l0, h1, l1, h2, l2, h3, l3;
    split2(acc.x, h0, l0); split2(acc.y, h1, l1);
    split2(acc.z, h2, l2); split2(acc.w, h3, l3);

    size_t o = (size_t)node * D + lane * 4;
    __nv_bfloat162* Ah2 = (__nv_bfloat162*)(g_Ahi + o);
    __nv_bfloat162* Al2 = (__nv_bfloat162*)(g_Alo + o);
    Ah2[0] = __nv_bfloat162(h0, h1);
    Ah2[1] = __nv_bfloat162(h2, h3);
    Al2[0] = __nv_bfloat162(l0, l1);
    Al2[1] = __nv_bfloat162(l2, l3);
}

// ===========================================================================
// Fused 2-layer GEMM, bf16x3, wmma. 256 threads / 8 warps.
// Warp tile 32 rows x 64 cols: wr = wid>>1 (rows 32wr..), wc = wid&1.
// All bf16 operands pre-split (A from gather, W from wsplit) -> staging = copy.
// ===========================================================================
#define LDA 136   // bf16 padded leading dim
#define LDH 132   // f32 padded leading dim

#define SM_BH   0
#define SM_BIAS 512                              // 16 x 128 f32 (replicated bo)
#define SM_AHI  (SM_BIAS + 16 * 128 * 4)         // 8704
#define SM_ALO  (SM_AHI + 128 * LDA * 2)
#define SM_WHI  (SM_ALO + 128 * LDA * 2)
#define SM_WLO  (SM_WHI + 128 * LDA * 2)
#define SM_HF   (SM_WLO + 128 * LDA * 2)
#define SM_TOTAL (SM_HF + 128 * LDH * 4)         // 8704 + 4*34816 + 67584 = 215552

typedef wmma::fragment<wmma::matrix_a, 16, 16, 16, __nv_bfloat16, wmma::row_major> FragA;
typedef wmma::fragment<wmma::matrix_b, 16, 16, 16, __nv_bfloat16, wmma::row_major> FragB;
typedef wmma::fragment<wmma::accumulator, 16, 16, 16, float> FragC;

__global__ __launch_bounds__(256, 1)
void fused_wmma_kernel(const float* __restrict__ bh, const float* __restrict__ bo,
                       float* __restrict__ out, int n_nodes) {
    extern __shared__ char smem[];
    float*          bh_s   = (float*)(smem + SM_BH);
    float*          bias_s = (float*)(smem + SM_BIAS);
    __nv_bfloat16*  Ahi    = (__nv_bfloat16*)(smem + SM_AHI);
    __nv_bfloat16*  Alo    = (__nv_bfloat16*)(smem + SM_ALO);
    __nv_bfloat16*  Whi    = (__nv_bfloat16*)(smem + SM_WHI);
    __nv_bfloat16*  Wlo    = (__nv_bfloat16*)(smem + SM_WLO);
    float*          Hf     = (float*)(smem + SM_HF);

    const int tid = threadIdx.x;
    const int wid = tid >> 5;
    const int row0 = blockIdx.x * 128;

    if (tid < 128) bh_s[tid] = bh[tid];
    #pragma unroll
    for (int it = 0; it < 8; ++it) {
        int i = tid + it * 256;                  // 2048 = 16 x 128
        bias_s[i] = bo[i & 127];
    }

    // --- stage A hi/lo (pure uint4 copies; rows past n_nodes zeroed) ---
    {
        const uint4* Gh = (const uint4*)g_Ahi;
        const uint4* Gl = (const uint4*)g_Alo;
        const uint4 z = make_uint4(0, 0, 0, 0);
        #pragma unroll
        for (int it = 0; it < 8; ++it) {
            int i = tid + it * 256;              // 2048 uint4 = 128r x 16
            int r = i >> 4, c8 = (i & 15) * 8;
            bool ok = (row0 + r < n_nodes);
            size_t gi = (size_t)(row0 + r) * 16 + (c8 >> 3);
            *(uint4*)&Ahi[r * LDA + c8] = ok ? Gh[gi] : z;
            *(uint4*)&Alo[r * LDA + c8] = ok ? Gl[gi] : z;
        }
    }
    // --- stage Wh hi/lo ---
    {
        const uint4* Gh = (const uint4*)g_Whhi;
        const uint4* Gl = (const uint4*)g_Whlo;
        #pragma unroll
        for (int it = 0; it < 8; ++it) {
            int i = tid + it * 256;
            int k = i >> 4, c8 = (i & 15) * 8;
            *(uint4*)&Whi[k * LDA + c8] = Gh[i];
            *(uint4*)&Wlo[k * LDA + c8] = Gl[i];
        }
    }
    __syncthreads();

    const int wr = wid >> 1;   // 0..3 -> rows 32wr
    const int wc = wid & 1;    // 0..1 -> cols 64wc

    // ---------------- GEMM 1 ----------------
    {
        FragC acc[2][4];
        #pragma unroll
        for (int r = 0; r < 2; ++r)
            #pragma unroll
            for (int n = 0; n < 4; ++n) wmma::fill_fragment(acc[r][n], 0.f);

        for (int k = 0; k < 8; ++k) {
            FragA ah0, ah1, al0, al1;
            wmma::load_matrix_sync(ah0, Ahi + (wr * 32 +  0) * LDA + k * 16, LDA);
            wmma::load_matrix_sync(ah1, Ahi + (wr * 32 + 16) * LDA + k * 16, LDA);
            wmma::load_matrix_sync(al0, Alo + (wr * 32 +  0) * LDA + k * 16, LDA);
            wmma::load_matrix_sync(al1, Alo + (wr * 32 + 16) * LDA + k * 16, LDA);
            #pragma unroll
            for (int n = 0; n < 4; ++n) {
                int nc = wc * 64 + n * 16;
                FragB b_hi, b_lo;
                wmma::load_matrix_sync(b_hi, Whi + k * 16 * LDA + nc, LDA);
                wmma::mma_sync(acc[0][n], ah0, b_hi, acc[0][n]);
                wmma::mma_sync(acc[1][n], ah1, b_hi, acc[1][n]);
                wmma::mma_sync(acc[0][n], al0, b_hi, acc[0][n]);
                wmma::mma_sync(acc[1][n], al1, b_hi, acc[1][n]);
                wmma::load_matrix_sync(b_lo, Wlo + k * 16 * LDA + nc, LDA);
                wmma::mma_sync(acc[0][n], ah0, b_lo, acc[0][n]);
                wmma::mma_sync(acc[1][n], ah1, b_lo, acc[1][n]);
            }
        }
        #pragma unroll
        for (int r = 0; r < 2; ++r)
            #pragma unroll
            for (int n = 0; n < 4; ++n)
                wmma::store_matrix_sync(Hf + (wr * 32 + r * 16) * LDH + wc * 64 + n * 16,
                                        acc[r][n], LDH, wmma::mem_row_major);
    }
    __syncthreads();

    // --- bias + relu + re-split H into A buffers; stage Wo over W ---
    #pragma unroll
    for (int it = 0; it < 16; ++it) {
        int i = tid + it * 256;                  // 4096 float4 = 128r x 32
        int r = i >> 5, c = (i & 31) * 4;
        float4 v = *(const float4*)&Hf[r * LDH + c];
        float x0 = fmaxf(v.x + bh_s[c + 0], 0.f);
        float x1 = fmaxf(v.y + bh_s[c + 1], 0.f);
        float x2 = fmaxf(v.z + bh_s[c + 2], 0.f);
        float x3 = fmaxf(v.w + bh_s[c + 3], 0.f);
        __nv_bfloat16 h0, l0, h1, l1, h2, l2, h3, l3;
        split2(x0, h0, l0); split2(x1, h1, l1);
        split2(x2, h2, l2); split2(x3, h3, l3);
        int o = r * LDA + c;
        Ahi[o] = h0; Ahi[o+1] = h1; Ahi[o+2] = h2; Ahi[o+3] = h3;
        Alo[o] = l0; Alo[o+1] = l1; Alo[o+2] = l2; Alo[o+3] = l3;
    }
    {
        const uint4* Gh = (const uint4*)g_Wohi;
        const uint4* Gl = (const uint4*)g_Wolo;
        #pragma unroll
        for (int it = 0; it < 8; ++it) {
            int i = tid + it * 256;
            int k = i >> 4, c8 = (i & 15) * 8;
            *(uint4*)&Whi[k * LDA + c8] = Gh[i];
            *(uint4*)&Wlo[k * LDA + c8] = Gl[i];
        }
    }
    __syncthreads();

    // ---------------- GEMM 2 (bias via accumulator init) ----------------
    {
        FragC acc[2][4];
        #pragma unroll
        for (int r = 0; r < 2; ++r)
            #pragma unroll
            for (int n = 0; n < 4; ++n)
                wmma::load_matrix_sync(acc[r][n], bias_s + wc * 64 + n * 16, 128,
                                       wmma::mem_row_major);

        for (int k = 0; k < 8; ++k) {
            FragA ah0, ah1, al0, al1;
            wmma::load_matrix_sync(ah0, Ahi + (wr * 32 +  0) * LDA + k * 16, LDA);
            wmma::load_matrix_sync(ah1, Ahi + (wr * 32 + 16) * LDA + k * 16, LDA);
            wmma::load_matrix_sync(al0, Alo + (wr * 32 +  0) * LDA + k * 16, LDA);
            wmma::load_matrix_sync(al1, Alo + (wr * 32 + 16) * LDA + k * 16, LDA);
            #pragma unroll
            for (int n = 0; n < 4; ++n) {
                int nc = wc * 64 + n * 16;
                FragB b_hi, b_lo;
                wmma::load_matrix_sync(b_hi, Whi + k * 16 * LDA + nc, LDA);
                wmma::mma_sync(acc[0][n], ah0, b_hi, acc[0][n]);
                wmma::mma_sync(acc[1][n], ah1, b_hi, acc[1][n]);
                wmma::mma_sync(acc[0][n], al0, b_hi, acc[0][n]);
                wmma::mma_sync(acc[1][n], al1, b_hi, acc[1][n]);
                wmma::load_matrix_sync(b_lo, Wlo + k * 16 * LDA + nc, LDA);
                wmma::mma_sync(acc[0][n], ah0, b_lo, acc[0][n]);
                wmma::mma_sync(acc[1][n], ah1, b_lo, acc[1][n]);
            }
        }

        if (row0 + 128 <= n_nodes) {
            // fast path: direct fragment store to gmem
            #pragma unroll
            for (int r = 0; r < 2; ++r) {
                float* Ot = out + (size_t)(row0 + wr * 32 + r * 16) * D + wc * 64;
                #pragma unroll
                for (int n = 0; n < 4; ++n)
                    wmma::store_matrix_sync(Ot + n * 16, acc[r][n], D, wmma::mem_row_major);
            }
        } else {
            // tail CTA: stage via Hf, guarded copy
            __syncthreads();
            #pragma unroll
            for (int r = 0; r < 2; ++r)
                #pragma unroll
                for (int n = 0; n < 4; ++n)
                    wmma::store_matrix_sync(Hf + (wr * 32 + r * 16) * LDH + wc * 64 + n * 16,
                                            acc[r][n], LDH, wmma::mem_row_major);
            __syncthreads();
            #pragma unroll
            for (int it = 0; it < 16; ++it) {
                int i = tid + it * 256;
                int r = i >> 5, c = (i & 31) * 4;
                if (row0 + r < n_nodes)
                    *(float4*)&out[(size_t)(row0 + r) * D + c] = *(float4*)&Hf[r * LDH + c];
            }
        }
    }
}

// ===========================================================================
extern "C" void kernel_launch(void* const* d_in, const int* in_sizes, int n_in,
                              void* d_out, int out_size) {
    const float* X  = (const float*)d_in[0];
    const int*   ra = (const int*)  d_in[1];
    const int*   rb = (const int*)  d_in[2];
    const float* Wh = (const float*)d_in[3];
    const float* bh = (const float*)d_in[4];
    const float* Wo = (const float*)d_in[5];
    const float* bo = (const float*)d_in[6];
    float* out = (float*)d_out;

    const int n_nodes = in_sizes[0] / D;
    const int n_edges = in_sizes[1];
    const int nb = (n_nodes + 1023) / 1024;
    const int gb = (n_nodes + 127) / 128;

    cudaFuncSetAttribute(fused_wmma_kernel,
                         cudaFuncAttributeMaxDynamicSharedMemorySize, SM_TOTAL);

    // weight pre-split (independent of graph; cheap)
    wsplit_kernel<<<64, 256>>>(Wh, Wo);

    // CSR build
    zero_deg_kernel<<<(n_nodes + 255) / 256, 256>>>(n_nodes);
    hist_kernel<<<(n_edges + 255) / 256, 256>>>(ra, rb, n_edges);
    scan_block_kernel<<<nb, 1024>>>(n_nodes);
    scan_top_kernel<<<1, 256>>>(nb);
    scan_add_kernel<<<nb, 1024>>>(n_nodes);
    fill_adj_kernel<<<(n_edges + 255) / 256, 256>>>(ra, rb, n_edges);

    // pull gather + split
    int gblocks = (int)(((size_t)n_nodes * 32 + 255) / 256);
    gather_kernel<<<gblocks, 256>>>((const float4*)X, n_nodes);

    // fused two-layer tensor-core GEMM
    fused_wmma_kernel<<<gb, 256, SM_TOTAL>>>(bh, bo, out, n_nodes);
}